// round 14
// baseline (speedup 1.0000x reference)
#include <cuda_runtime.h>
#include <cstdint>

#define T_LEN 64000
#define NB 4
#define CH 128
#define NCLS 256
#define CHUNK 32
#define NCHUNK 8
#define NITER 16                  // (chunk, tap)
#define SPAN 256
#define NXCTA (T_LEN / SPAN)      // 250
#define NCHK (T_LEN / CHUNK)      // 2000 scale chunks per n

// stage geometry (int8): row stride 144 B (16-aligned), plane = 32*144
#define STG_STRIDE 144
#define STG_PLANE  4608

// ---------------- static device buffers ----------------
__device__ int8_t g_actq0[(size_t)NB * 2 * T_LEN * CH];
__device__ int8_t g_actq1[(size_t)NB * 2 * T_LEN * CH];
__device__ float  g_xs0[NB * NCHK];
__device__ float  g_xs1[NB * NCHK];
__device__ int8_t g_wq[27 * 2 * 2 * 128 * 128];   // [L][pl][tap][m][ch]
__device__ int8_t g_wcq[2 * 256 * 128];           // [pl][cls][ch]
__device__ unsigned g_wmaxb[27 * 2];              // |w| max bits per (L,tap)
__device__ unsigned g_wcmaxb[1];

#define DEQC (1.f / (16256.f * 32512.f))

// ---------------- helpers ----------------
__device__ __forceinline__ uint32_t smem_u32(const void* p) {
    uint32_t a;
    asm("{ .reg .u64 t; cvta.to.shared.u64 t, %1; cvt.u32.u64 %0, t; }" : "=r"(a) : "l"(p));
    return a;
}
__device__ __forceinline__ void cpa16(uint32_t dst, const void* src, int sz) {
    asm volatile("cp.async.cg.shared.global [%0], [%1], 16, %2;"
                 :: "r"(dst), "l"(src), "r"(sz) : "memory");
}
#define CP_COMMIT() asm volatile("cp.async.commit_group;" ::: "memory")
#define CP_WAIT1()  asm volatile("cp.async.wait_group 1;" ::: "memory")
#define CP_WAIT0()  asm volatile("cp.async.wait_group 0;" ::: "memory")

// int8 MMA: A = weights (s8), B = activations (u8), s32 accumulate, K=32
__device__ __forceinline__ void imma(int c[4], const uint32_t a[4],
                                     uint32_t b0, uint32_t b1) {
    asm volatile(
        "mma.sync.aligned.m16n8k32.row.col.s32.s8.u8.s32 "
        "{%0,%1,%2,%3}, {%4,%5,%6,%7}, {%8,%9}, {%0,%1,%2,%3};"
        : "+r"(c[0]), "+r"(c[1]), "+r"(c[2]), "+r"(c[3])
        : "r"(a[0]), "r"(a[1]), "r"(a[2]), "r"(a[3]), "r"(b0), "r"(b1));
}

// ---------------- prep 1: weight abs-max per (L,tap) ----------------
__global__ void prep_max(const float* __restrict__ wrest,
                         const float* __restrict__ wcls,
                         unsigned* __restrict__ wmaxb,
                         unsigned* __restrict__ wcmaxb) {
    int idx = blockIdx.x * blockDim.x + threadIdx.x;
    if (idx < 27 * 2 * 128 * 128) {
        int L = idx >> 15;
        int tap = (idx >> 14) & 1;
        int m = (idx >> 7) & 127;
        int ch = idx & 127;
        float w = wrest[((L * 128 + m) * 128 + ch) * 2 + tap];
        atomicMax(wmaxb + L * 2 + tap, __float_as_uint(fabsf(w)));
    }
    if (idx < 256 * 128)
        atomicMax(wcmaxb, __float_as_uint(fabsf(wcls[idx])));
}

// ---------------- prep 2: quantize weights to two int8 planes ----------------
__global__ void prep_quant(const float* __restrict__ wrest,
                           const float* __restrict__ wcls,
                           const unsigned* __restrict__ wmaxb,
                           const unsigned* __restrict__ wcmaxb,
                           int8_t* __restrict__ wq,
                           int8_t* __restrict__ wcq) {
    int idx = blockIdx.x * blockDim.x + threadIdx.x;
    if (idx < 27 * 2 * 128 * 128) {
        int L = idx >> 15;
        int tap = (idx >> 14) & 1;
        int m = (idx >> 7) & 127;
        int ch = idx & 127;
        float w = wrest[((L * 128 + m) * 128 + ch) * 2 + tap];
        float wm = __uint_as_float(wmaxb[L * 2 + tap]);
        float Sw = 16256.f / fmaxf(wm, 1e-30f);
        int qw = __float2int_rn(w * Sw);
        int w1 = (qw + 64) >> 7;
        int w2 = qw - (w1 << 7);
        size_t base = (((size_t)L * 2) * 2 + tap) * 128 * 128 + (size_t)m * 128 + ch;
        wq[base] = (int8_t)w1;                          // plane 0
        wq[base + (size_t)2 * 128 * 128] = (int8_t)w2;  // plane 1
    }
    if (idx < 256 * 128) {
        float w = wcls[idx];
        float wm = __uint_as_float(wcmaxb[0]);
        float Sw = 16256.f / fmaxf(wm, 1e-30f);
        int qw = __float2int_rn(w * Sw);
        int w1 = (qw + 64) >> 7;
        int w2 = qw - (w1 << 7);
        wcq[idx] = (int8_t)w1;
        wcq[idx + 256 * 128] = (int8_t)w2;
    }
}

// ---------------- layer 0: fp32 -> quantized int8 planes + scale ----------------
__global__ void layer0_q(const float* __restrict__ seq,
                         const float* __restrict__ wf,
                         int8_t* __restrict__ xout,
                         float* __restrict__ xsout) {
    __shared__ float red[8];
    int tid = threadIdx.x;
    int oc = tid & 127, hh = tid >> 7;
    int wid = tid >> 5, lane = tid & 31;
    int n = blockIdx.y;
    int tcb = blockIdx.x * CHUNK;
    float w0 = wf[oc * 2], w1 = wf[oc * 2 + 1];
    const float* xs = seq + (size_t)n * T_LEN;

    float y[16];
    float lmax = 0.f;
#pragma unroll
    for (int j = 0; j < 16; j++) {
        int t = tcb + hh * 16 + j;
        float xv1 = xs[t];
        float xv0 = (t >= 1) ? xs[t - 1] : 0.f;
        y[j] = fmaxf(w0 * xv0 + w1 * xv1, 0.f);
        lmax = fmaxf(lmax, y[j]);
    }
#pragma unroll
    for (int o = 16; o; o >>= 1) lmax = fmaxf(lmax, __shfl_xor_sync(~0u, lmax, o));
    if (lane == 0) red[wid] = lmax;
    __syncthreads();
    float cmax = red[0];
#pragma unroll
    for (int w = 1; w < 8; w++) cmax = fmaxf(cmax, red[w]);
    float S = 32512.f / fmaxf(cmax, 1e-30f);

    int8_t* o0 = xout + ((size_t)(n * 2 + 0) * T_LEN) * CH;
    int8_t* o1 = xout + ((size_t)(n * 2 + 1) * T_LEN) * CH;
#pragma unroll
    for (int j = 0; j < 16; j++) {
        int t = tcb + hh * 16 + j;
        int q = min(__float2int_rn(y[j] * S), 32512);
        o0[(size_t)t * CH + oc] = (int8_t)(q >> 7);
        o1[(size_t)t * CH + oc] = (int8_t)(q & 127);
    }
    if (tid == 0) xsout[n * NCHK + blockIdx.x] = cmax;
}

// ---------------- dilated-conv layer, int8 MMA ----------------
// smem (u32): [0,18432) W [pl2][tap2][m128][36]; [18432,23040) X [buf2][pl2][32][36];
//             stage int8 [23040, +2304) (2 planes x 32 x 144B); red at 25344
__global__ void __launch_bounds__(256, 1) layer_q(
    const int8_t* __restrict__ xin, const float* __restrict__ xsin,
    int8_t* __restrict__ xout, float* __restrict__ xsout,
    const uint32_t* __restrict__ wq, const unsigned* __restrict__ wmaxb, int d) {
    extern __shared__ uint32_t sm[];
    const uint32_t sb = smem_u32(sm);
    const int tid = threadIdx.x;
    const int lane = tid & 31, wid = tid >> 5;
    const int g = lane >> 2, tq = lane & 3;
    const int n = blockIdx.y;
    const int tbase = blockIdx.x * SPAN;
    const int m0 = (wid & 3) * 32;
    const int n0 = (wid >> 2) * 16;
    const float* xsn = xsin + n * NCHK;
    const float invW0 = __uint_as_float(__ldg(wmaxb + 0)) * DEQC;
    const float invW1 = __uint_as_float(__ldg(wmaxb + 1)) * DEQC;

    // W -> smem (4096 segs)
#pragma unroll
    for (int i = 0; i < 16; i++) {
        int idx = i * 256 + tid;
        int row = idx >> 3, segi = idx & 7;   // row = (pl*2+tap)*128 + m
        cpa16(sb + (row * 36 + segi * 4) * 4, wq + row * 32 + segi * 4, 16);
    }
    CP_COMMIT();

    auto load_xt = [&](int it) {
        int c = it >> 1, tap = it & 1, buf = it & 1;
        int tcb = tbase + c * CHUNK;
#pragma unroll
        for (int i = 0; i < 2; i++) {
            int idx = i * 256 + tid;           // 512 segs
            int pl = idx >> 8, rem = idx & 255;
            int r = rem >> 3, segi = rem & 7;
            int t = tcb + r - (tap == 0 ? d : 0);
            const int8_t* src =
                xin + ((size_t)(n * 2 + pl) * T_LEN + (t < 0 ? 0 : t)) * CH + segi * 16;
            cpa16(sb + (18432 + (buf * 2 + pl) * 1152 + r * 36 + segi * 4) * 4,
                  src, t >= 0 ? 16 : 0);
        }
        CP_COMMIT();
    };
    load_xt(0);
    load_xt(1);
    CP_WAIT1();
    __syncthreads();

    int8_t* stg = (int8_t*)(sm + 23040);
    float* red = (float*)(sm + 25344);

    int acc[2][3][2][2][4];    // [tap][P1/P2/P3][mt][nt][ci]

#pragma unroll 1
    for (int it = 0; it < NITER; it++) {
        const int tap = it & 1, buf = it & 1;
        const uint32_t* Xb = sm + 18432 + buf * 2304;

        if (tap == 0) {
#pragma unroll
            for (int tp = 0; tp < 2; tp++)
#pragma unroll
                for (int p = 0; p < 3; p++)
#pragma unroll
                    for (int mt = 0; mt < 2; mt++)
#pragma unroll
                        for (int nt = 0; nt < 2; nt++)
#pragma unroll
                            for (int j = 0; j < 4; j++) acc[tp][p][mt][nt][j] = 0;
        }

        const uint32_t* W1 = sm + tap * 128 * 36;           // plane 0
        const uint32_t* W2 = sm + (2 + tap) * 128 * 36;     // plane 1
        const uint32_t* X1 = Xb;                            // plane 0 (x1)
        const uint32_t* X2 = Xb + 1152;                     // plane 1 (x2)
#pragma unroll
        for (int ks = 0; ks < 4; ks++) {
            uint32_t a1[2][4], a2[2][4];
            uint32_t b1l[2], b1h[2], b2l[2], b2h[2];
#pragma unroll
            for (int mt = 0; mt < 2; mt++) {
                int r0 = (m0 + mt * 16 + g) * 36, r1 = (m0 + mt * 16 + g + 8) * 36;
                a1[mt][0] = W1[r0 + ks * 8 + tq];
                a1[mt][1] = W1[r1 + ks * 8 + tq];
                a1[mt][2] = W1[r0 + ks * 8 + 4 + tq];
                a1[mt][3] = W1[r1 + ks * 8 + 4 + tq];
                a2[mt][0] = W2[r0 + ks * 8 + tq];
                a2[mt][1] = W2[r1 + ks * 8 + tq];
                a2[mt][2] = W2[r0 + ks * 8 + 4 + tq];
                a2[mt][3] = W2[r1 + ks * 8 + 4 + tq];
            }
#pragma unroll
            for (int nt = 0; nt < 2; nt++) {
                int xr = (n0 + nt * 8 + g) * 36 + ks * 8;
                b1l[nt] = X1[xr + tq];
                b1h[nt] = X1[xr + 4 + tq];
                b2l[nt] = X2[xr + tq];
                b2h[nt] = X2[xr + 4 + tq];
            }
            // P1 = w1*x1; P2 = w2*x1 + w1*x2 (shared acc); P3 = w2*x2
#pragma unroll
            for (int mt = 0; mt < 2; mt++)
#pragma unroll
                for (int nt = 0; nt < 2; nt++)
                    imma(acc[tap][0][mt][nt], a1[mt], b1l[nt], b1h[nt]);
#pragma unroll
            for (int mt = 0; mt < 2; mt++)
#pragma unroll
                for (int nt = 0; nt < 2; nt++)
                    imma(acc[tap][1][mt][nt], a2[mt], b1l[nt], b1h[nt]);
#pragma unroll
            for (int mt = 0; mt < 2; mt++)
#pragma unroll
                for (int nt = 0; nt < 2; nt++)
                    imma(acc[tap][1][mt][nt], a1[mt], b2l[nt], b2h[nt]);
#pragma unroll
            for (int mt = 0; mt < 2; mt++)
#pragma unroll
                for (int nt = 0; nt < 2; nt++)
                    imma(acc[tap][2][mt][nt], a2[mt], b2l[nt], b2h[nt]);
        }

        __syncthreads();  // X[buf] reads done; stage/red reuse safe

        if (it + 2 < NITER) load_xt(it + 2);

        if (tap == 1) {
            const int c = it >> 1;
            const int tcb = tbase + c * CHUNK;
            // dequant + relu
            float yv[2][2][4];
            float lmax = 0.f;
#pragma unroll
            for (int mt = 0; mt < 2; mt++)
#pragma unroll
                for (int nt = 0; nt < 2; nt++)
#pragma unroll
                    for (int ci = 0; ci < 4; ci++) {
                        int tl = n0 + nt * 8 + tq * 2 + (ci & 1);
                        int tg = tcb + tl;
                        int i0 = tg - d; i0 = (i0 < 0 ? 0 : i0) >> 5;
                        float K0 = __ldg(xsn + i0) * invW0;
                        float K1 = __ldg(xsn + (tg >> 5)) * invW1;
                        float y =
                            ((float)acc[0][0][mt][nt][ci] * 16384.f +
                             (float)acc[0][1][mt][nt][ci] * 128.f +
                             (float)acc[0][2][mt][nt][ci]) * K0 +
                            ((float)acc[1][0][mt][nt][ci] * 16384.f +
                             (float)acc[1][1][mt][nt][ci] * 128.f +
                             (float)acc[1][2][mt][nt][ci]) * K1;
                        y = fmaxf(y, 0.f);
                        yv[mt][nt][ci] = y;
                        lmax = fmaxf(lmax, y);
                    }
#pragma unroll
            for (int o = 16; o; o >>= 1)
                lmax = fmaxf(lmax, __shfl_xor_sync(~0u, lmax, o));
            if (lane == 0) red[wid] = lmax;
            __syncthreads();
            float cmax = red[0];
#pragma unroll
            for (int w = 1; w < 8; w++) cmax = fmaxf(cmax, red[w]);
            float S = 32512.f / fmaxf(cmax, 1e-30f);
#pragma unroll
            for (int mt = 0; mt < 2; mt++)
#pragma unroll
                for (int nt = 0; nt < 2; nt++)
#pragma unroll
                    for (int ci = 0; ci < 4; ci++) {
                        int m = m0 + mt * 16 + g + ((ci >> 1) * 8);
                        int tl = n0 + nt * 8 + tq * 2 + (ci & 1);
                        int q = min(__float2int_rn(yv[mt][nt][ci] * S), 32512);
                        stg[tl * STG_STRIDE + m] = (int8_t)(q >> 7);
                        stg[STG_PLANE + tl * STG_STRIDE + m] = (int8_t)(q & 127);
                    }
            if (tid == 0) xsout[n * NCHK + (tcb >> 5)] = cmax;

            if (it + 1 < NITER) {
                if (it + 2 < NITER) CP_WAIT1();
                else CP_WAIT0();
            }
            __syncthreads();

            // coalesced uint4 stores (overlap next MMA)
#pragma unroll
            for (int i = 0; i < 2; i++) {
                int idx = i * 256 + tid;       // 512 uint4
                int pl = idx >> 8, rem = idx & 255;
                int r = rem >> 3, sg = rem & 7;
                uint4 v = *(const uint4*)(stg + pl * STG_PLANE + r * STG_STRIDE +
                                          sg * 16);
                *(uint4*)(xout + ((size_t)(n * 2 + pl) * T_LEN + tcb + r) * CH +
                          sg * 16) = v;
            }
        } else {
            if (it + 1 < NITER) {
                if (it + 2 < NITER) CP_WAIT1();
                else CP_WAIT0();
            }
            __syncthreads();
        }
    }
}

// ---------------- classifier: int8 in, fp32 out + bias ----------------
// smem (u32): [0,9216) Wc [pl2][128][36]; [9216,13824) X [buf2][pl2][32][36];
//             [13824,18176) stage f32 [128][34]
__global__ void __launch_bounds__(256, 1) cls_q(
    const int8_t* __restrict__ xin, const float* __restrict__ xsin,
    const uint32_t* __restrict__ wcq, const unsigned* __restrict__ wcmaxb,
    const float* __restrict__ bias, float* __restrict__ out) {
    extern __shared__ uint32_t sm[];
    const uint32_t sb = smem_u32(sm);
    const int tid = threadIdx.x;
    const int lane = tid & 31, wid = tid >> 5;
    const int g = lane >> 2, tq = lane & 3;
    const int n = blockIdx.y;
    const int tbase = blockIdx.x * SPAN;
    const int mz = blockIdx.z * 128;
    const int m0 = (wid & 3) * 32;
    const int n0 = (wid >> 2) * 16;
    const float* xsn = xsin + n * NCHK;
    const float invW = __uint_as_float(__ldg(wcmaxb)) * DEQC;

#pragma unroll
    for (int i = 0; i < 8; i++) {
        int idx = i * 256 + tid;               // 2048 segs
        int row = idx >> 3, segi = idx & 7;    // row = pl*128 + mr
        int pl = row >> 7, mr = row & 127;
        cpa16(sb + (row * 36 + segi * 4) * 4,
              wcq + ((size_t)(pl * 256 + mz + mr) * 32 + segi * 4), 16);
    }
    CP_COMMIT();

    auto load_x = [&](int c) {
        int buf = c & 1;
        int tcb = tbase + c * CHUNK;
#pragma unroll
        for (int i = 0; i < 2; i++) {
            int idx = i * 256 + tid;
            int pl = idx >> 8, rem = idx & 255;
            int r = rem >> 3, segi = rem & 7;
            const int8_t* src =
                xin + ((size_t)(n * 2 + pl) * T_LEN + tcb + r) * CH + segi * 16;
            cpa16(sb + (9216 + (buf * 2 + pl) * 1152 + r * 36 + segi * 4) * 4, src, 16);
        }
        CP_COMMIT();
    };
    load_x(0);
    load_x(1);
    CP_WAIT1();
    __syncthreads();

    float* stg = (float*)(sm + 13824);

#pragma unroll 1
    for (int c = 0; c < NCHUNK; c++) {
        const int buf = c & 1;
        const uint32_t* Xb = sm + 9216 + buf * 2304;

        int acc[3][2][2][4];
#pragma unroll
        for (int p = 0; p < 3; p++)
#pragma unroll
            for (int mt = 0; mt < 2; mt++)
#pragma unroll
                for (int nt = 0; nt < 2; nt++)
#pragma unroll
                    for (int j = 0; j < 4; j++) acc[p][mt][nt][j] = 0;

        const uint32_t* W1 = sm;
        const uint32_t* W2 = sm + 128 * 36;
        const uint32_t* X1 = Xb;
        const uint32_t* X2 = Xb + 1152;
#pragma unroll
        for (int ks = 0; ks < 4; ks++) {
            uint32_t a1[2][4], a2[2][4];
            uint32_t b1l[2], b1h[2], b2l[2], b2h[2];
#pragma unroll
            for (int mt = 0; mt < 2; mt++) {
                int r0 = (m0 + mt * 16 + g) * 36, r1 = (m0 + mt * 16 + g + 8) * 36;
                a1[mt][0] = W1[r0 + ks * 8 + tq];
                a1[mt][1] = W1[r1 + ks * 8 + tq];
                a1[mt][2] = W1[r0 + ks * 8 + 4 + tq];
                a1[mt][3] = W1[r1 + ks * 8 + 4 + tq];
                a2[mt][0] = W2[r0 + ks * 8 + tq];
                a2[mt][1] = W2[r1 + ks * 8 + tq];
                a2[mt][2] = W2[r0 + ks * 8 + 4 + tq];
                a2[mt][3] = W2[r1 + ks * 8 + 4 + tq];
            }
#pragma unroll
            for (int nt = 0; nt < 2; nt++) {
                int xr = (n0 + nt * 8 + g) * 36 + ks * 8;
                b1l[nt] = X1[xr + tq];
                b1h[nt] = X1[xr + 4 + tq];
                b2l[nt] = X2[xr + tq];
                b2h[nt] = X2[xr + 4 + tq];
            }
#pragma unroll
            for (int mt = 0; mt < 2; mt++)
#pragma unroll
                for (int nt = 0; nt < 2; nt++) {
                    imma(acc[0][mt][nt], a1[mt], b1l[nt], b1h[nt]);
                    imma(acc[1][mt][nt], a2[mt], b1l[nt], b1h[nt]);
                    imma(acc[1][mt][nt], a1[mt], b2l[nt], b2h[nt]);
                    imma(acc[2][mt][nt], a2[mt], b2l[nt], b2h[nt]);
                }
        }

        __syncthreads();
        if (c + 2 < NCHUNK) load_x(c + 2);

        const int tcb = tbase + c * CHUNK;
        float Kc = __ldg(xsn + (tcb >> 5)) * invW;
#pragma unroll
        for (int mt = 0; mt < 2; mt++)
#pragma unroll
            for (int nt = 0; nt < 2; nt++)
#pragma unroll
                for (int ci = 0; ci < 4; ci++) {
                    int m = m0 + mt * 16 + g + ((ci >> 1) * 8);
                    int tl = n0 + nt * 8 + tq * 2 + (ci & 1);
                    float y = ((float)acc[0][mt][nt][ci] * 16384.f +
                               (float)acc[1][mt][nt][ci] * 128.f +
                               (float)acc[2][mt][nt][ci]) * Kc +
                              __ldg(bias + mz + m);
                    stg[m * 34 + tl] = y;
                }

        if (c + 1 < NCHUNK) {
            if (c + 2 < NCHUNK) CP_WAIT1();
            else CP_WAIT0();
        }
        __syncthreads();

#pragma unroll
        for (int i = 0; i < 8; i++) {
            int idx = i * 256 + tid;
            int row = idx >> 4, sg = idx & 15;
            float2 v = *(const float2*)(stg + row * 34 + sg * 2);
            *(float2*)(out + ((size_t)n * NCLS + mz + row) * T_LEN + tcb + sg * 2) = v;
        }
    }
}

// ---------------- launch ----------------
extern "C" void kernel_launch(void* const* d_in, const int* in_sizes, int n_in,
                              void* d_out, int out_size) {
    (void)in_sizes; (void)n_in; (void)out_size;
    const float* seq     = (const float*)d_in[0];
    const float* w_first = (const float*)d_in[1];
    const float* w_rest  = (const float*)d_in[2];
    const float* w_cls   = (const float*)d_in[3];
    const float* b_cls   = (const float*)d_in[4];
    float* out = (float*)d_out;

    int8_t *q0, *q1, *wq, *wcq;
    float *xs0, *xs1;
    unsigned *wmaxb, *wcmaxb;
    cudaGetSymbolAddress((void**)&q0, g_actq0);
    cudaGetSymbolAddress((void**)&q1, g_actq1);
    cudaGetSymbolAddress((void**)&xs0, g_xs0);
    cudaGetSymbolAddress((void**)&xs1, g_xs1);
    cudaGetSymbolAddress((void**)&wq, g_wq);
    cudaGetSymbolAddress((void**)&wcq, g_wcq);
    cudaGetSymbolAddress((void**)&wmaxb, g_wmaxb);
    cudaGetSymbolAddress((void**)&wcmaxb, g_wcmaxb);

    const int smem_layer = 25352 * 4;   // 101408 B
    const int smem_cls   = 18176 * 4;   // 72704 B
    cudaFuncSetAttribute(layer_q, cudaFuncAttributeMaxDynamicSharedMemorySize, smem_layer);
    cudaFuncSetAttribute(cls_q, cudaFuncAttributeMaxDynamicSharedMemorySize, smem_cls);

    prep_max<<<(27 * 2 * 128 * 128 + 255) / 256, 256>>>(w_rest, w_cls, wmaxb, wcmaxb);
    prep_quant<<<(27 * 2 * 128 * 128 + 255) / 256, 256>>>(w_rest, w_cls, wmaxb, wcmaxb,
                                                          wq, wcq);
    layer0_q<<<dim3(NCHK, NB), 256>>>(seq, w_first, q0, xs0);

    for (int i = 1; i < 28; i++) {
        int l = i % 14;
        int d = 1 << (l % 10);
        const int8_t* xi = (i & 1) ? q0 : q1;
        int8_t* xo       = (i & 1) ? q1 : q0;
        const float* si  = (i & 1) ? xs0 : xs1;
        float* so        = (i & 1) ? xs1 : xs0;
        layer_q<<<dim3(NXCTA, NB), 256, smem_layer>>>(
            xi, si, xo, so,
            (const uint32_t*)(wq + (size_t)(i - 1) * 2 * 2 * 128 * 128),
            wmaxb + (i - 1) * 2, d);
    }

    cls_q<<<dim3(NXCTA, NB, 2), 256, smem_cls>>>(q1, xs1, (const uint32_t*)wcq,
                                                 wcmaxb, b_cls, out);
}

// round 15
// speedup vs baseline: 3.8317x; 3.8317x over previous
#include <cuda_runtime.h>
#include <cuda_fp16.h>
#include <cstdint>

#define T_LEN 64000
#define NB 4
#define CH 128
#define NCLS 256
#define LCH 128                  // t per chunk (layer kernel)
#define NITER 8                  // (chunk, tap, xplane) sub-iters: 2 chunks x 4
#define SPAN 256                 // t per CTA
#define NXCTA (T_LEN / SPAN)     // 250
// classifier
#define CCH 32
#define CNCH 8

// ---------------- static device buffers ----------------
__device__ unsigned short g_act0[(size_t)NB * 2 * T_LEN * CH];
__device__ unsigned short g_act1[(size_t)NB * 2 * T_LEN * CH];
__device__ uint32_t g_whi[27 * 2 * 128 * 64];
__device__ uint32_t g_wlo[27 * 2 * 128 * 64];
__device__ uint32_t g_wc[2 * 256 * 64];

// ---------------- helpers ----------------
__device__ __forceinline__ uint32_t smem_u32(const void* p) {
    uint32_t a;
    asm("{ .reg .u64 t; cvta.to.shared.u64 t, %1; cvt.u32.u64 %0, t; }" : "=r"(a) : "l"(p));
    return a;
}
__device__ __forceinline__ void cpa16(uint32_t dst, const void* src, int sz) {
    asm volatile("cp.async.cg.shared.global [%0], [%1], 16, %2;"
                 :: "r"(dst), "l"(src), "r"(sz) : "memory");
}
#define CP_COMMIT() asm volatile("cp.async.commit_group;" ::: "memory")
#define CP_WAIT1()  asm volatile("cp.async.wait_group 1;" ::: "memory")
#define CP_WAIT0()  asm volatile("cp.async.wait_group 0;" ::: "memory")

__device__ __forceinline__ void mmaf32(float c[4], const uint32_t a[4],
                                       uint32_t b0, uint32_t b1) {
    asm volatile(
        "mma.sync.aligned.m16n8k16.row.col.f32.f16.f16.f32 "
        "{%0,%1,%2,%3}, {%4,%5,%6,%7}, {%8,%9}, {%0,%1,%2,%3};"
        : "+f"(c[0]), "+f"(c[1]), "+f"(c[2]), "+f"(c[3])
        : "r"(a[0]), "r"(a[1]), "r"(a[2]), "r"(a[3]), "r"(b0), "r"(b1));
}
__device__ __forceinline__ void mmaf16(uint32_t c[2], const uint32_t a[4],
                                       uint32_t b0, uint32_t b1) {
    asm volatile(
        "mma.sync.aligned.m16n8k16.row.col.f16.f16.f16.f16 "
        "{%0,%1}, {%2,%3,%4,%5}, {%6,%7}, {%0,%1};"
        : "+r"(c[0]), "+r"(c[1])
        : "r"(a[0]), "r"(a[1]), "r"(a[2]), "r"(a[3]), "r"(b0), "r"(b1));
}
__device__ __forceinline__ float h2get(uint32_t reg, int hi) {
    __half2 h = *reinterpret_cast<__half2*>(&reg);
    return hi ? __high2float(h) : __low2float(h);
}

// ---------------- prep: split + pack fp16 weights ----------------
__device__ __forceinline__ uint32_t pack_split(float w0, float w1, int plane) {
    __half h0 = __float2half_rn(w0), h1 = __float2half_rn(w1);
    if (plane == 0)
        return (uint32_t)__half_as_ushort(h0) |
               ((uint32_t)__half_as_ushort(h1) << 16);
    __half l0 = __float2half_rn(w0 - __half2float(h0));
    __half l1 = __float2half_rn(w1 - __half2float(h1));
    return (uint32_t)__half_as_ushort(l0) |
           ((uint32_t)__half_as_ushort(l1) << 16);
}

__global__ void prep_kernel(const float* __restrict__ wrest,
                            const float* __restrict__ wcls,
                            uint32_t* __restrict__ whi,
                            uint32_t* __restrict__ wlo,
                            uint32_t* __restrict__ wc) {
    int idx = blockIdx.x * blockDim.x + threadIdx.x;
    if (idx < 27 * 2 * 128 * 64) {
        int kp = idx & 63;
        int m = (idx >> 6) & 127;
        int tap = (idx >> 13) & 1;
        int L = idx >> 14;
        float w0 = wrest[((L * 128 + m) * 128 + kp * 2) * 2 + tap];
        float w1 = wrest[((L * 128 + m) * 128 + kp * 2 + 1) * 2 + tap];
        whi[idx] = pack_split(w0, w1, 0);
        wlo[idx] = pack_split(w0, w1, 1);
    }
    if (idx < 2 * 256 * 64) {
        int kp = idx & 63;
        int m = (idx >> 6) & 255;
        int pl = idx >> 14;
        float w0 = wcls[m * 128 + kp * 2];
        float w1 = wcls[m * 128 + kp * 2 + 1];
        wc[idx] = pack_split(w0, w1, pl);
    }
}

// ---------------- layer 0 ----------------
__global__ void layer0_kernel(const float* __restrict__ seq,
                              const float* __restrict__ wf,
                              unsigned short* __restrict__ actout) {
    int oc = threadIdx.x & 127;
    int half_ = threadIdx.x >> 7;
    int n = blockIdx.y;
    int t0 = blockIdx.x * 128 + half_ * 64;
    float w0 = wf[oc * 2], w1 = wf[oc * 2 + 1];
    const float* xs = seq + (size_t)n * T_LEN;
    unsigned short* ohi = actout + (size_t)(n * 2 + 0) * T_LEN * CH;
    unsigned short* olo = actout + (size_t)(n * 2 + 1) * T_LEN * CH;
    for (int j = 0; j < 64; j++) {
        int t = t0 + j;
        float x1 = xs[t];
        float x0 = (t >= 1) ? xs[t - 1] : 0.f;
        float y = fmaxf(w0 * x0 + w1 * x1, 0.f);
        __half h = __float2half_rn(y);
        __half l = __float2half_rn(y - __half2float(h));
        ohi[(size_t)t * CH + oc] = __half_as_ushort(h);
        olo[(size_t)t * CH + oc] = __half_as_ushort(l);
    }
}

// ---------------- dilated-conv layer, 512 threads, 16 warps ----------------
// smem (u32 units):
//   [0, 34816)        W : [pl 2][tap 2][m 128][68]
//   [34816, 52224)    X : [buf 2][t 128][68]     (one (tap,xplane) per buf)
//   [52224, 56576)    stage: u16[2 pl][32 t][136 m]
// warps: 4(m of 32) x 4(n of 32); CTA tile 128m x 128t; acc persists over 4 sub-iters.
// Products: wh*xh (f32 acc), wh*xl + wl*xh (shared f16 acc).
__global__ void __launch_bounds__(512, 1) layer_mma(
    const unsigned short* __restrict__ actin,
    unsigned short* __restrict__ actout,
    const uint32_t* __restrict__ whi,
    const uint32_t* __restrict__ wlo, int d) {
    extern __shared__ uint32_t sm[];
    const uint32_t sb = smem_u32(sm);
    const int tid = threadIdx.x;
    const int lane = tid & 31, wid = tid >> 5;
    const int g = lane >> 2, tq = lane & 3;
    const int n = blockIdx.y;
    const int tbase = blockIdx.x * SPAN;
    const int m0 = (wid & 3) * 32;
    const int n0 = (wid >> 2) * 32;

    // ---- W (both planes) -> smem: 8192 segs of 16B
#pragma unroll
    for (int i = 0; i < 16; i++) {
        int idx = i * 512 + tid;
        int row = idx >> 4, seg = idx & 15;   // row = pl*256 + tap*128 + m
        const uint32_t* src = ((row < 256) ? whi : wlo) + (row & 255) * 64 + seg * 4;
        cpa16(sb + (row * 68 + seg * 4) * 4, src, 16);
    }
    CP_COMMIT();

    // ---- per-sub-iter X loader: one plane of one tap, 128 t rows
    auto load_x = [&](int s) {
        int c = s >> 2, tap = (s >> 1) & 1, xpl = s & 1, buf = s & 1;
        int tcb = tbase + c * LCH;
#pragma unroll
        for (int i = 0; i < 4; i++) {
            int idx = i * 512 + tid;          // 2048 segs
            int r = idx >> 4, seg = idx & 15;
            int t = tcb + r - (tap == 0 ? d : 0);
            const unsigned short* src =
                actin + ((size_t)(n * 2 + xpl) * T_LEN + (t < 0 ? 0 : t)) * CH + seg * 8;
            cpa16(sb + (34816 + buf * 8704 + r * 68 + seg * 4) * 4,
                  src, t >= 0 ? 16 : 0);
        }
        CP_COMMIT();
    };
    load_x(0);
    load_x(1);

    CP_WAIT1();          // W + sub-iter0 complete (sub-iter1 in flight)
    __syncthreads();

    unsigned short* stg = (unsigned short*)(sm + 52224);

    float accf[2][4][4];       // main wh*xh (f32 acc) [mt][nt][ci]
    uint32_t acch[2][4][2];    // corrections shared f16 acc [mt][nt][2]

#pragma unroll 1
    for (int s = 0; s < NITER; s++) {
        const int tap = (s >> 1) & 1, xpl = s & 1, buf = s & 1;
        const uint32_t* X = sm + 34816 + buf * 8704;

        if ((s & 3) == 0) {
#pragma unroll
            for (int mt = 0; mt < 2; mt++)
#pragma unroll
                for (int nt = 0; nt < 4; nt++) {
#pragma unroll
                    for (int j = 0; j < 4; j++) accf[mt][nt][j] = 0.f;
                    acch[mt][nt][0] = 0u;
                    acch[mt][nt][1] = 0u;
                }
        }

        const uint32_t* Wh = sm + tap * 8704;           // plane hi, this tap
        const uint32_t* Wl = sm + 17408 + tap * 8704;   // plane lo, this tap
#pragma unroll
        for (int ks = 0; ks < 8; ks++) {
            uint32_t b0[4], b1[4];
#pragma unroll
            for (int nt = 0; nt < 4; nt++) {
                int xr = (n0 + nt * 8 + g) * 68 + ks * 8;
                b0[nt] = X[xr + tq];
                b1[nt] = X[xr + 4 + tq];
            }
            uint32_t ah[2][4];
#pragma unroll
            for (int mt = 0; mt < 2; mt++) {
                int r0 = (m0 + mt * 16 + g) * 68, r1 = (m0 + mt * 16 + g + 8) * 68;
                ah[mt][0] = Wh[r0 + ks * 8 + tq];
                ah[mt][1] = Wh[r1 + ks * 8 + tq];
                ah[mt][2] = Wh[r0 + ks * 8 + 4 + tq];
                ah[mt][3] = Wh[r1 + ks * 8 + 4 + tq];
            }
            if (xpl == 0) {
                // main: wh * xh (f32 acc)
#pragma unroll
                for (int mt = 0; mt < 2; mt++)
#pragma unroll
                    for (int nt = 0; nt < 4; nt++)
                        mmaf32(accf[mt][nt], ah[mt], b0[nt], b1[nt]);
                // correction: wl * xh (f16 acc)
                uint32_t al[2][4];
#pragma unroll
                for (int mt = 0; mt < 2; mt++) {
                    int r0 = (m0 + mt * 16 + g) * 68, r1 = (m0 + mt * 16 + g + 8) * 68;
                    al[mt][0] = Wl[r0 + ks * 8 + tq];
                    al[mt][1] = Wl[r1 + ks * 8 + tq];
                    al[mt][2] = Wl[r0 + ks * 8 + 4 + tq];
                    al[mt][3] = Wl[r1 + ks * 8 + 4 + tq];
                }
#pragma unroll
                for (int mt = 0; mt < 2; mt++)
#pragma unroll
                    for (int nt = 0; nt < 4; nt++)
                        mmaf16(acch[mt][nt], al[mt], b0[nt], b1[nt]);
            } else {
                // correction: wh * xl (f16 acc, shared)
#pragma unroll
                for (int mt = 0; mt < 2; mt++)
#pragma unroll
                    for (int nt = 0; nt < 4; nt++)
                        mmaf16(acch[mt][nt], ah[mt], b0[nt], b1[nt]);
            }
        }

        __syncthreads();   // X[buf] reads done by all warps

        if (s + 2 < NITER) load_x(s + 2);

        if ((s & 3) == 3) {
            // chunk complete: epilogue in 4 waves of 32 t
            const int tcb = tbase + (s >> 2) * LCH;
#pragma unroll
            for (int h = 0; h < 4; h++) {
                if (n0 == h * 32) {
#pragma unroll
                    for (int mt = 0; mt < 2; mt++)
#pragma unroll
                        for (int nt = 0; nt < 4; nt++)
#pragma unroll
                            for (int ci = 0; ci < 4; ci++) {
                                int m = m0 + mt * 16 + g + ((ci >> 1) * 8);
                                int tl = nt * 8 + tq * 2 + (ci & 1);  // local 0..31
                                float y = accf[mt][nt][ci] +
                                          h2get(acch[mt][nt][ci >> 1], ci & 1);
                                y = fmaxf(y, 0.f);
                                __half hh = __float2half_rn(y);
                                __half ll = __float2half_rn(y - __half2float(hh));
                                stg[tl * 136 + m] = __half_as_ushort(hh);
                                stg[4352 + tl * 136 + m] = __half_as_ushort(ll);
                            }
                }
                if (h == 3 && s + 1 < NITER) {
                    if (s + 2 < NITER) CP_WAIT1();
                    else CP_WAIT0();
                }
                __syncthreads();   // stage visible (+ next sub-iter data on h==3)
#pragma unroll
                for (int i = 0; i < 2; i++) {
                    int idx = i * 512 + tid;    // 1024 uint4 per wave
                    int pl = idx >> 9, rem = idx & 511;
                    int r = rem >> 4, sg = rem & 15;
                    uint4 v = *(const uint4*)(stg + pl * 4352 + r * 136 + sg * 8);
                    *(uint4*)(actout +
                              ((size_t)(n * 2 + pl) * T_LEN + tcb + h * 32 + r) * CH +
                              sg * 8) = v;
                }
                if (h < 3) __syncthreads();  // stage reads done before next wave writes
            }
        } else {
            if (s + 1 < NITER) {
                if (s + 2 < NITER) CP_WAIT1();
                else CP_WAIT0();
            }
            __syncthreads();   // next sub-iter's X visible
        }
    }
}

// ---------------- classifier: 128 -> 256, + bias, no relu (256 threads) ----------------
__global__ void __launch_bounds__(256, 1) cls_mma(
    const unsigned short* __restrict__ actin,
    const uint32_t* __restrict__ wc,
    const float* __restrict__ bias,
    float* __restrict__ out) {
    extern __shared__ uint32_t sm[];
    const uint32_t sb = smem_u32(sm);
    const int tid = threadIdx.x;
    const int lane = tid & 31, wid = tid >> 5;
    const int g = lane >> 2, tq = lane & 3;
    const int n = blockIdx.y;
    const int tbase = blockIdx.x * SPAN;
    const int mz = blockIdx.z * 128;
    const int m0 = (wid & 3) * 32;
    const int n0 = (wid >> 2) * 16;

#pragma unroll
    for (int i = 0; i < 16; i++) {
        int idx = i * 256 + tid;
        int row = idx >> 4, seg = idx & 15;
        const uint32_t* src = wc + ((size_t)(row >> 7) * 256 + mz + (row & 127)) * 64 + seg * 4;
        cpa16(sb + (row * 68 + seg * 4) * 4, src, 16);
    }
    CP_COMMIT();

    auto load_x = [&](int c) {
        int buf = c & 1;
        int tcb = tbase + c * CCH;
#pragma unroll
        for (int i = 0; i < 4; i++) {
            int idx = i * 256 + tid;
            int pl = idx >> 9, rem = idx & 511;
            int r = rem >> 4, seg = rem & 15;
            const unsigned short* src =
                actin + ((size_t)(n * 2 + pl) * T_LEN + tcb + r) * CH + seg * 8;
            cpa16(sb + (17408 + buf * 4352 + pl * 2176 + r * 68 + seg * 4) * 4, src, 16);
        }
        CP_COMMIT();
    };
    load_x(0);
    load_x(1);
    CP_WAIT1();
    __syncthreads();

    float* stg = (float*)(sm + 26112);

#pragma unroll 1
    for (int c = 0; c < CNCH; c++) {
        const int buf = c & 1;
        const uint32_t* X = sm + 17408 + buf * 4352;

        float acc[3][2][2][4];
#pragma unroll
        for (int p = 0; p < 3; p++)
#pragma unroll
            for (int mt = 0; mt < 2; mt++)
#pragma unroll
                for (int nt = 0; nt < 2; nt++)
#pragma unroll
                    for (int j = 0; j < 4; j++) acc[p][mt][nt][j] = 0.f;

        const uint32_t* Wh = sm;
        const uint32_t* Wl = sm + 8704;
        const uint32_t* Xh = X;
        const uint32_t* Xl = X + 2176;
#pragma unroll
        for (int ks = 0; ks < 8; ks++) {
            uint32_t ah[2][4], al[2][4];
            uint32_t bh0[2], bh1[2], bl0[2], bl1[2];
#pragma unroll
            for (int mt = 0; mt < 2; mt++) {
                int r0 = (m0 + mt * 16 + g) * 68, r1 = (m0 + mt * 16 + g + 8) * 68;
                ah[mt][0] = Wh[r0 + ks * 8 + tq];
                ah[mt][1] = Wh[r1 + ks * 8 + tq];
                ah[mt][2] = Wh[r0 + ks * 8 + 4 + tq];
                ah[mt][3] = Wh[r1 + ks * 8 + 4 + tq];
                al[mt][0] = Wl[r0 + ks * 8 + tq];
                al[mt][1] = Wl[r1 + ks * 8 + tq];
                al[mt][2] = Wl[r0 + ks * 8 + 4 + tq];
                al[mt][3] = Wl[r1 + ks * 8 + 4 + tq];
            }
#pragma unroll
            for (int nt = 0; nt < 2; nt++) {
                int xr = (n0 + nt * 8 + g) * 68;
                bh0[nt] = Xh[xr + ks * 8 + tq];
                bh1[nt] = Xh[xr + ks * 8 + 4 + tq];
                bl0[nt] = Xl[xr + ks * 8 + tq];
                bl1[nt] = Xl[xr + ks * 8 + 4 + tq];
            }
#pragma unroll
            for (int mt = 0; mt < 2; mt++)
#pragma unroll
                for (int nt = 0; nt < 2; nt++)
                    mmaf32(acc[0][mt][nt], ah[mt], bh0[nt], bh1[nt]);
#pragma unroll
            for (int mt = 0; mt < 2; mt++)
#pragma unroll
                for (int nt = 0; nt < 2; nt++)
                    mmaf32(acc[1][mt][nt], ah[mt], bl0[nt], bl1[nt]);
#pragma unroll
            for (int mt = 0; mt < 2; mt++)
#pragma unroll
                for (int nt = 0; nt < 2; nt++)
                    mmaf32(acc[2][mt][nt], al[mt], bh0[nt], bh1[nt]);
        }

        __syncthreads();
        if (c + 2 < CNCH) load_x(c + 2);

#pragma unroll
        for (int mt = 0; mt < 2; mt++)
#pragma unroll
            for (int nt = 0; nt < 2; nt++)
#pragma unroll
                for (int ci = 0; ci < 4; ci++) {
                    int m = m0 + mt * 16 + g + ((ci >> 1) * 8);
                    int tl = n0 + nt * 8 + tq * 2 + (ci & 1);
                    float y = acc[0][mt][nt][ci] + acc[1][mt][nt][ci] + acc[2][mt][nt][ci];
                    stg[m * 34 + tl] = y + __ldg(bias + mz + m);
                }

        if (c + 1 < CNCH) {
            if (c + 2 < CNCH) CP_WAIT1();
            else CP_WAIT0();
        }
        __syncthreads();

        const int tcb = tbase + c * CCH;
#pragma unroll
        for (int i = 0; i < 8; i++) {
            int idx = i * 256 + tid;
            int row = idx >> 4, sg = idx & 15;
            float2 v = *(const float2*)(stg + row * 34 + sg * 2);
            *(float2*)(out + ((size_t)n * NCLS + mz + row) * T_LEN + tcb + sg * 2) = v;
        }
    }
}

// ---------------- launch ----------------
extern "C" void kernel_launch(void* const* d_in, const int* in_sizes, int n_in,
                              void* d_out, int out_size) {
    (void)in_sizes; (void)n_in; (void)out_size;
    const float* seq     = (const float*)d_in[0];
    const float* w_first = (const float*)d_in[1];
    const float* w_rest  = (const float*)d_in[2];
    const float* w_cls   = (const float*)d_in[3];
    const float* b_cls   = (const float*)d_in[4];
    float* out = (float*)d_out;

    unsigned short *a0, *a1;
    uint32_t *whi, *wlo, *wc;
    cudaGetSymbolAddress((void**)&a0, g_act0);
    cudaGetSymbolAddress((void**)&a1, g_act1);
    cudaGetSymbolAddress((void**)&whi, g_whi);
    cudaGetSymbolAddress((void**)&wlo, g_wlo);
    cudaGetSymbolAddress((void**)&wc, g_wc);

    const int smem_layer = 56576 * 4;  // 226304 B
    const int smem_cls   = 30464 * 4;  // 121856 B
    cudaFuncSetAttribute(layer_mma, cudaFuncAttributeMaxDynamicSharedMemorySize, smem_layer);
    cudaFuncSetAttribute(cls_mma, cudaFuncAttributeMaxDynamicSharedMemorySize, smem_cls);

    prep_kernel<<<(27 * 2 * 128 * 64 + 255) / 256, 256>>>(w_rest, w_cls, whi, wlo, wc);
    layer0_kernel<<<dim3(T_LEN / 128, NB), 256>>>(seq, w_first, a0);

    for (int i = 1; i < 28; i++) {
        int l = i % 14;
        int d = 1 << (l % 10);
        const unsigned short* src = (i & 1) ? a0 : a1;
        unsigned short* dst       = (i & 1) ? a1 : a0;
        layer_mma<<<dim3(NXCTA, NB), 512, smem_layer>>>(
            src, dst, whi + (size_t)(i - 1) * 2 * 128 * 64,
            wlo + (size_t)(i - 1) * 2 * 128 * 64, d);
    }

    cls_mma<<<dim3(NXCTA, NB, 2), 256, smem_cls>>>(a1, wc, b_cls, out);
}

// round 16
// speedup vs baseline: 5.0579x; 1.3200x over previous
#include <cuda_runtime.h>
#include <cuda_fp16.h>
#include <cstdint>

#define T_LEN 64000
#define NB 4
#define CH 128
#define NCLS 256
#define CHUNK 64
#define NITER 8                   // (chunk, tap) pairs
#define SPAN 256                  // t per CTA
#define NXCTA (T_LEN / SPAN)      // 250
// classifier
#define CCH 32
#define CNCH 8

// ---------------- static device buffers ----------------
__device__ unsigned short g_act0[(size_t)NB * 2 * T_LEN * CH];
__device__ unsigned short g_act1[(size_t)NB * 2 * T_LEN * CH];
__device__ uint32_t g_whi[27 * 2 * 128 * 64];
__device__ uint32_t g_wc[2 * 256 * 64];

// ---------------- helpers ----------------
__device__ __forceinline__ uint32_t smem_u32(const void* p) {
    uint32_t a;
    asm("{ .reg .u64 t; cvta.to.shared.u64 t, %1; cvt.u32.u64 %0, t; }" : "=r"(a) : "l"(p));
    return a;
}
__device__ __forceinline__ void cpa16(uint32_t dst, const void* src, int sz) {
    asm volatile("cp.async.cg.shared.global [%0], [%1], 16, %2;"
                 :: "r"(dst), "l"(src), "r"(sz) : "memory");
}
#define CP_COMMIT() asm volatile("cp.async.commit_group;" ::: "memory")
#define CP_WAIT1()  asm volatile("cp.async.wait_group 1;" ::: "memory")
#define CP_WAIT0()  asm volatile("cp.async.wait_group 0;" ::: "memory")

__device__ __forceinline__ void mmaf32(float c[4], const uint32_t a[4],
                                       uint32_t b0, uint32_t b1) {
    asm volatile(
        "mma.sync.aligned.m16n8k16.row.col.f32.f16.f16.f32 "
        "{%0,%1,%2,%3}, {%4,%5,%6,%7}, {%8,%9}, {%0,%1,%2,%3};"
        : "+f"(c[0]), "+f"(c[1]), "+f"(c[2]), "+f"(c[3])
        : "r"(a[0]), "r"(a[1]), "r"(a[2]), "r"(a[3]), "r"(b0), "r"(b1));
}

// ---------------- prep: pack fp16 weights (hi plane for layers; both for cls) ----------------
__device__ __forceinline__ uint32_t pack_split(float w0, float w1, int plane) {
    __half h0 = __float2half_rn(w0), h1 = __float2half_rn(w1);
    if (plane == 0)
        return (uint32_t)__half_as_ushort(h0) |
               ((uint32_t)__half_as_ushort(h1) << 16);
    __half l0 = __float2half_rn(w0 - __half2float(h0));
    __half l1 = __float2half_rn(w1 - __half2float(h1));
    return (uint32_t)__half_as_ushort(l0) |
           ((uint32_t)__half_as_ushort(l1) << 16);
}

__global__ void prep_kernel(const float* __restrict__ wrest,
                            const float* __restrict__ wcls,
                            uint32_t* __restrict__ whi,
                            uint32_t* __restrict__ wc) {
    int idx = blockIdx.x * blockDim.x + threadIdx.x;
    if (idx < 27 * 2 * 128 * 64) {
        int kp = idx & 63;
        int m = (idx >> 6) & 127;
        int tap = (idx >> 13) & 1;
        int L = idx >> 14;
        float w0 = wrest[((L * 128 + m) * 128 + kp * 2) * 2 + tap];
        float w1 = wrest[((L * 128 + m) * 128 + kp * 2 + 1) * 2 + tap];
        whi[idx] = pack_split(w0, w1, 0);
    }
    if (idx < 2 * 256 * 64) {
        int kp = idx & 63;
        int m = (idx >> 6) & 255;
        int pl = idx >> 14;
        float w0 = wcls[m * 128 + kp * 2];
        float w1 = wcls[m * 128 + kp * 2 + 1];
        wc[idx] = pack_split(w0, w1, pl);
    }
}

// ---------------- layer 0 ----------------
__global__ void layer0_kernel(const float* __restrict__ seq,
                              const float* __restrict__ wf,
                              unsigned short* __restrict__ actout) {
    int oc = threadIdx.x & 127;
    int half_ = threadIdx.x >> 7;
    int n = blockIdx.y;
    int t0 = blockIdx.x * 128 + half_ * 64;
    float w0 = wf[oc * 2], w1 = wf[oc * 2 + 1];
    const float* xs = seq + (size_t)n * T_LEN;
    unsigned short* ohi = actout + (size_t)(n * 2 + 0) * T_LEN * CH;
    unsigned short* olo = actout + (size_t)(n * 2 + 1) * T_LEN * CH;
    for (int j = 0; j < 64; j++) {
        int t = t0 + j;
        float x1 = xs[t];
        float x0 = (t >= 1) ? xs[t - 1] : 0.f;
        float y = fmaxf(w0 * x0 + w1 * x1, 0.f);
        __half h = __float2half_rn(y);
        __half l = __float2half_rn(y - __half2float(h));
        ohi[(size_t)t * CH + oc] = __half_as_ushort(h);
        olo[(size_t)t * CH + oc] = __half_as_ushort(l);
    }
}

// ---------------- dilated-conv layer: 2-product fp16 MMA ----------------
// smem (u32 units):
//   [0, 17408)        Wh : [tap 2][m 128][68]
//   [17408, 34816)    X  : [buf 2][pl 2][r 64][68]   (buf = tap parity)
//   [34816, 39168)    stage: u16[2 pl][32 t][136 m]
// chunk = 64 t; 8 warps = 4(m of 32) x 2(n of 32); acc persists across taps.
// Products kept: wh*xh + wh*xl (both f32 acc). wl terms dropped.
__global__ void __launch_bounds__(256, 1) layer_mma(
    const unsigned short* __restrict__ actin,
    unsigned short* __restrict__ actout,
    const uint32_t* __restrict__ whi, int d) {
    extern __shared__ uint32_t sm[];
    const uint32_t sb = smem_u32(sm);
    const int tid = threadIdx.x;
    const int lane = tid & 31, wid = tid >> 5;
    const int g = lane >> 2, tq = lane & 3;
    const int n = blockIdx.y;
    const int tbase = blockIdx.x * SPAN;
    const int m0 = (wid & 3) * 32;
    const int n0 = (wid >> 2) * 32;

    // ---- Wh -> smem: 4096 segs of 16B
#pragma unroll
    for (int i = 0; i < 16; i++) {
        int idx = i * 256 + tid;
        int row = idx >> 4, seg = idx & 15;   // row = tap*128 + m
        cpa16(sb + (row * 68 + seg * 4) * 4, whi + row * 64 + seg * 4, 16);
    }
    CP_COMMIT();

    // ---- per-(chunk,tap) X loader: 2 planes x 64 t
    auto load_xt = [&](int it) {
        int c = it >> 1, tap = it & 1, buf = it & 1;
        int tcb = tbase + c * CHUNK;
#pragma unroll
        for (int i = 0; i < 8; i++) {
            int idx = i * 256 + tid;          // 2048 segs
            int pl = idx >> 10, rem = idx & 1023;
            int r = rem >> 4, seg = rem & 15;
            int t = tcb + r - (tap == 0 ? d : 0);
            const unsigned short* src =
                actin + ((size_t)(n * 2 + pl) * T_LEN + (t < 0 ? 0 : t)) * CH + seg * 8;
            cpa16(sb + (17408 + buf * 8704 + pl * 4352 + r * 68 + seg * 4) * 4,
                  src, t >= 0 ? 16 : 0);
        }
        CP_COMMIT();
    };
    load_xt(0);
    load_xt(1);

    CP_WAIT1();          // W + iter0 complete (iter1 in flight)
    __syncthreads();

    unsigned short* stg = (unsigned short*)(sm + 34816);

    float acc[2][2][4][4];   // [product xh/xl][mt][nt][ci]

#pragma unroll 1
    for (int it = 0; it < NITER; it++) {
        const int tap = it & 1, buf = it & 1;
        const uint32_t* Xb = sm + 17408 + buf * 8704;

        if (tap == 0) {
#pragma unroll
            for (int p = 0; p < 2; p++)
#pragma unroll
                for (int mt = 0; mt < 2; mt++)
#pragma unroll
                    for (int nt = 0; nt < 4; nt++)
#pragma unroll
                        for (int j = 0; j < 4; j++) acc[p][mt][nt][j] = 0.f;
        }

        const uint32_t* Wh = sm + tap * 8704;
        const uint32_t* Xh = Xb;
        const uint32_t* Xl = Xb + 4352;
#pragma unroll
        for (int ks = 0; ks < 8; ks++) {
            uint32_t ah[2][4];
            uint32_t bh0[4], bh1[4], bl0[4], bl1[4];
#pragma unroll
            for (int mt = 0; mt < 2; mt++) {
                int r0 = (m0 + mt * 16 + g) * 68, r1 = (m0 + mt * 16 + g + 8) * 68;
                ah[mt][0] = Wh[r0 + ks * 8 + tq];
                ah[mt][1] = Wh[r1 + ks * 8 + tq];
                ah[mt][2] = Wh[r0 + ks * 8 + 4 + tq];
                ah[mt][3] = Wh[r1 + ks * 8 + 4 + tq];
            }
#pragma unroll
            for (int nt = 0; nt < 4; nt++) {
                int xr = (n0 + nt * 8 + g) * 68;
                bh0[nt] = Xh[xr + ks * 8 + tq];
                bh1[nt] = Xh[xr + ks * 8 + 4 + tq];
                bl0[nt] = Xl[xr + ks * 8 + tq];
                bl1[nt] = Xl[xr + ks * 8 + 4 + tq];
            }
            // 16 independent MMAs
#pragma unroll
            for (int mt = 0; mt < 2; mt++)
#pragma unroll
                for (int nt = 0; nt < 4; nt++)
                    mmaf32(acc[0][mt][nt], ah[mt], bh0[nt], bh1[nt]);
#pragma unroll
            for (int mt = 0; mt < 2; mt++)
#pragma unroll
                for (int nt = 0; nt < 4; nt++)
                    mmaf32(acc[1][mt][nt], ah[mt], bl0[nt], bl1[nt]);
        }

        __syncthreads();   // all warps done reading X[buf]; stage reads done

        if (it + 2 < NITER) load_xt(it + 2);

        if (tap == 1) {
            // epilogue for chunk c in two 32-t waves
            const int tcb = tbase + (it >> 1) * CHUNK;
#pragma unroll
            for (int h = 0; h < 2; h++) {
                if (n0 == h * 32) {
#pragma unroll
                    for (int mt = 0; mt < 2; mt++)
#pragma unroll
                        for (int nt = 0; nt < 4; nt++)
#pragma unroll
                            for (int ci = 0; ci < 4; ci++) {
                                int m = m0 + mt * 16 + g + ((ci >> 1) * 8);
                                int tl = nt * 8 + tq * 2 + (ci & 1);  // 0..31 local
                                float y = acc[0][mt][nt][ci] + acc[1][mt][nt][ci];
                                y = fmaxf(y, 0.f);
                                __half hh = __float2half_rn(y);
                                __half ll = __float2half_rn(y - __half2float(hh));
                                stg[tl * 136 + m] = __half_as_ushort(hh);
                                stg[4352 + tl * 136 + m] = __half_as_ushort(ll);
                            }
                }
                if (h == 1 && it + 1 < NITER) {
                    if (it + 2 < NITER) CP_WAIT1();
                    else CP_WAIT0();
                }
                __syncthreads();   // stage visible (+ next iter data on h==1)
#pragma unroll
                for (int i = 0; i < 4; i++) {
                    int idx = i * 256 + tid;   // 1024 uint4 per wave
                    int pl = idx >> 9, rem = idx & 511;
                    int r = rem >> 4, sg = rem & 15;
                    uint4 v = *(const uint4*)(stg + pl * 4352 + r * 136 + sg * 8);
                    *(uint4*)(actout +
                              ((size_t)(n * 2 + pl) * T_LEN + tcb + h * 32 + r) * CH +
                              sg * 8) = v;
                }
                if (h == 0) __syncthreads();  // wave-0 stage reads before wave-1 rewrite
            }
        } else {
            if (it + 1 < NITER) {
                if (it + 2 < NITER) CP_WAIT1();
                else CP_WAIT0();
            }
            __syncthreads();   // next iter's X visible
        }
    }
}

// ---------------- classifier: 128 -> 256, full 3-product, + bias ----------------
// smem (u32): [0,17408) WC [pl][128][68]; [17408,26112) X [buf2][pl2][32][68];
//             [26112,30464) stage f32 [128][34]
__global__ void __launch_bounds__(256, 1) cls_mma(
    const unsigned short* __restrict__ actin,
    const uint32_t* __restrict__ wc,
    const float* __restrict__ bias,
    float* __restrict__ out) {
    extern __shared__ uint32_t sm[];
    const uint32_t sb = smem_u32(sm);
    const int tid = threadIdx.x;
    const int lane = tid & 31, wid = tid >> 5;
    const int g = lane >> 2, tq = lane & 3;
    const int n = blockIdx.y;
    const int tbase = blockIdx.x * SPAN;
    const int mz = blockIdx.z * 128;
    const int m0 = (wid & 3) * 32;
    const int n0 = (wid >> 2) * 16;

#pragma unroll
    for (int i = 0; i < 16; i++) {
        int idx = i * 256 + tid;
        int row = idx >> 4, seg = idx & 15;
        const uint32_t* src = wc + ((size_t)(row >> 7) * 256 + mz + (row & 127)) * 64 + seg * 4;
        cpa16(sb + (row * 68 + seg * 4) * 4, src, 16);
    }
    CP_COMMIT();

    auto load_x = [&](int c) {
        int buf = c & 1;
        int tcb = tbase + c * CCH;
#pragma unroll
        for (int i = 0; i < 4; i++) {
            int idx = i * 256 + tid;
            int pl = idx >> 9, rem = idx & 511;
            int r = rem >> 4, seg = rem & 15;
            const unsigned short* src =
                actin + ((size_t)(n * 2 + pl) * T_LEN + tcb + r) * CH + seg * 8;
            cpa16(sb + (17408 + buf * 4352 + pl * 2176 + r * 68 + seg * 4) * 4, src, 16);
        }
        CP_COMMIT();
    };
    load_x(0);
    load_x(1);
    CP_WAIT1();
    __syncthreads();

    float* stg = (float*)(sm + 26112);

#pragma unroll 1
    for (int c = 0; c < CNCH; c++) {
        const int buf = c & 1;
        const uint32_t* X = sm + 17408 + buf * 4352;

        float acc[3][2][2][4];
#pragma unroll
        for (int p = 0; p < 3; p++)
#pragma unroll
            for (int mt = 0; mt < 2; mt++)
#pragma unroll
                for (int nt = 0; nt < 2; nt++)
#pragma unroll
                    for (int j = 0; j < 4; j++) acc[p][mt][nt][j] = 0.f;

        const uint32_t* Wh = sm;
        const uint32_t* Wl = sm + 8704;
        const uint32_t* Xh = X;
        const uint32_t* Xl = X + 2176;
#pragma unroll
        for (int ks = 0; ks < 8; ks++) {
            uint32_t ah[2][4], al[2][4];
            uint32_t bh0[2], bh1[2], bl0[2], bl1[2];
#pragma unroll
            for (int mt = 0; mt < 2; mt++) {
                int r0 = (m0 + mt * 16 + g) * 68, r1 = (m0 + mt * 16 + g + 8) * 68;
                ah[mt][0] = Wh[r0 + ks * 8 + tq];
                ah[mt][1] = Wh[r1 + ks * 8 + tq];
                ah[mt][2] = Wh[r0 + ks * 8 + 4 + tq];
                ah[mt][3] = Wh[r1 + ks * 8 + 4 + tq];
                al[mt][0] = Wl[r0 + ks * 8 + tq];
                al[mt][1] = Wl[r1 + ks * 8 + tq];
                al[mt][2] = Wl[r0 + ks * 8 + 4 + tq];
                al[mt][3] = Wl[r1 + ks * 8 + 4 + tq];
            }
#pragma unroll
            for (int nt = 0; nt < 2; nt++) {
                int xr = (n0 + nt * 8 + g) * 68;
                bh0[nt] = Xh[xr + ks * 8 + tq];
                bh1[nt] = Xh[xr + ks * 8 + 4 + tq];
                bl0[nt] = Xl[xr + ks * 8 + tq];
                bl1[nt] = Xl[xr + ks * 8 + 4 + tq];
            }
#pragma unroll
            for (int mt = 0; mt < 2; mt++)
#pragma unroll
                for (int nt = 0; nt < 2; nt++)
                    mmaf32(acc[0][mt][nt], ah[mt], bh0[nt], bh1[nt]);
#pragma unroll
            for (int mt = 0; mt < 2; mt++)
#pragma unroll
                for (int nt = 0; nt < 2; nt++)
                    mmaf32(acc[1][mt][nt], ah[mt], bl0[nt], bl1[nt]);
#pragma unroll
            for (int mt = 0; mt < 2; mt++)
#pragma unroll
                for (int nt = 0; nt < 2; nt++)
                    mmaf32(acc[2][mt][nt], al[mt], bh0[nt], bh1[nt]);
        }

        __syncthreads();
        if (c + 2 < CNCH) load_x(c + 2);

#pragma unroll
        for (int mt = 0; mt < 2; mt++)
#pragma unroll
            for (int nt = 0; nt < 2; nt++)
#pragma unroll
                for (int ci = 0; ci < 4; ci++) {
                    int m = m0 + mt * 16 + g + ((ci >> 1) * 8);
                    int tl = n0 + nt * 8 + tq * 2 + (ci & 1);
                    float y = acc[0][mt][nt][ci] + acc[1][mt][nt][ci] + acc[2][mt][nt][ci];
                    stg[m * 34 + tl] = y + __ldg(bias + mz + m);
                }

        if (c + 1 < CNCH) {
            if (c + 2 < CNCH) CP_WAIT1();
            else CP_WAIT0();
        }
        __syncthreads();

        const int tcb = tbase + c * CCH;
#pragma unroll
        for (int i = 0; i < 8; i++) {
            int idx = i * 256 + tid;
            int row = idx >> 4, sg = idx & 15;
            float2 v = *(const float2*)(stg + row * 34 + sg * 2);
            *(float2*)(out + ((size_t)n * NCLS + mz + row) * T_LEN + tcb + sg * 2) = v;
        }
    }
}

// ---------------- launch ----------------
extern "C" void kernel_launch(void* const* d_in, const int* in_sizes, int n_in,
                              void* d_out, int out_size) {
    (void)in_sizes; (void)n_in; (void)out_size;
    const float* seq     = (const float*)d_in[0];
    const float* w_first = (const float*)d_in[1];
    const float* w_rest  = (const float*)d_in[2];
    const float* w_cls   = (const float*)d_in[3];
    const float* b_cls   = (const float*)d_in[4];
    float* out = (float*)d_out;

    unsigned short *a0, *a1;
    uint32_t *whi, *wc;
    cudaGetSymbolAddress((void**)&a0, g_act0);
    cudaGetSymbolAddress((void**)&a1, g_act1);
    cudaGetSymbolAddress((void**)&whi, g_whi);
    cudaGetSymbolAddress((void**)&wc, g_wc);

    const int smem_layer = 39168 * 4;  // 156672 B
    const int smem_cls   = 30464 * 4;  // 121856 B
    cudaFuncSetAttribute(layer_mma, cudaFuncAttributeMaxDynamicSharedMemorySize, smem_layer);
    cudaFuncSetAttribute(cls_mma, cudaFuncAttributeMaxDynamicSharedMemorySize, smem_cls);

    prep_kernel<<<(27 * 2 * 128 * 64 + 255) / 256, 256>>>(w_rest, w_cls, whi, wc);
    layer0_kernel<<<dim3(T_LEN / 128, NB), 256>>>(seq, w_first, a0);

    for (int i = 1; i < 28; i++) {
        int l = i % 14;
        int d = 1 << (l % 10);
        const unsigned short* src = (i & 1) ? a0 : a1;
        unsigned short* dst       = (i & 1) ? a1 : a0;
        layer_mma<<<dim3(NXCTA, NB), 256, smem_layer>>>(
            src, dst, whi + (size_t)(i - 1) * 2 * 128 * 64, d);
    }

    cls_mma<<<dim3(NXCTA, NB, 2), 256, smem_cls>>>(a1, wc, b_cls, out);
}

// round 17
// speedup vs baseline: 5.1474x; 1.0177x over previous
#include <cuda_runtime.h>
#include <cuda_fp16.h>
#include <cstdint>

#define T_LEN 64000
#define NB 4
#define CH 128
#define NCLS 256
#define CHUNK 64
#define NITER 8                   // (chunk, tap) pairs
#define SPAN 256                  // t per CTA
#define NXCTA (T_LEN / SPAN)      // 250
// classifier
#define CCH 32
#define CNCH 8

// ---------------- static device buffers ----------------
__device__ unsigned short g_act0[(size_t)NB * 2 * T_LEN * CH];
__device__ unsigned short g_act1[(size_t)NB * 2 * T_LEN * CH];
__device__ uint32_t g_whi[27 * 2 * 128 * 64];
__device__ uint32_t g_wc[2 * 256 * 64];

// ---------------- helpers ----------------
__device__ __forceinline__ uint32_t smem_u32(const void* p) {
    uint32_t a;
    asm("{ .reg .u64 t; cvta.to.shared.u64 t, %1; cvt.u32.u64 %0, t; }" : "=r"(a) : "l"(p));
    return a;
}
__device__ __forceinline__ void cpa16(uint32_t dst, const void* src, int sz) {
    asm volatile("cp.async.cg.shared.global [%0], [%1], 16, %2;"
                 :: "r"(dst), "l"(src), "r"(sz) : "memory");
}
#define CP_COMMIT() asm volatile("cp.async.commit_group;" ::: "memory")
#define CP_WAIT1()  asm volatile("cp.async.wait_group 1;" ::: "memory")
#define CP_WAIT0()  asm volatile("cp.async.wait_group 0;" ::: "memory")

__device__ __forceinline__ void mmaf32(float c[4], const uint32_t a[4],
                                       uint32_t b0, uint32_t b1) {
    asm volatile(
        "mma.sync.aligned.m16n8k16.row.col.f32.f16.f16.f32 "
        "{%0,%1,%2,%3}, {%4,%5,%6,%7}, {%8,%9}, {%0,%1,%2,%3};"
        : "+f"(c[0]), "+f"(c[1]), "+f"(c[2]), "+f"(c[3])
        : "r"(a[0]), "r"(a[1]), "r"(a[2]), "r"(a[3]), "r"(b0), "r"(b1));
}

// ---------------- prep: pack fp16 weights (hi plane only) ----------------
__global__ void prep_kernel(const float* __restrict__ wrest,
                            const float* __restrict__ wcls,
                            uint32_t* __restrict__ whi,
                            uint32_t* __restrict__ wc) {
    int idx = blockIdx.x * blockDim.x + threadIdx.x;
    if (idx < 27 * 2 * 128 * 64) {
        int kp = idx & 63;
        int m = (idx >> 6) & 127;
        int tap = (idx >> 13) & 1;
        int L = idx >> 14;
        float w0 = wrest[((L * 128 + m) * 128 + kp * 2) * 2 + tap];
        float w1 = wrest[((L * 128 + m) * 128 + kp * 2 + 1) * 2 + tap];
        __half h0 = __float2half_rn(w0), h1 = __float2half_rn(w1);
        whi[idx] = (uint32_t)__half_as_ushort(h0) |
                   ((uint32_t)__half_as_ushort(h1) << 16);
    }
    if (idx < 256 * 64) {
        int kp = idx & 63;
        int m = idx >> 6;
        float w0 = wcls[m * 128 + kp * 2];
        float w1 = wcls[m * 128 + kp * 2 + 1];
        __half h0 = __float2half_rn(w0), h1 = __float2half_rn(w1);
        wc[idx] = (uint32_t)__half_as_ushort(h0) |
                  ((uint32_t)__half_as_ushort(h1) << 16);
    }
}

// ---------------- layer 0 ----------------
__global__ void layer0_kernel(const float* __restrict__ seq,
                              const float* __restrict__ wf,
                              unsigned short* __restrict__ actout) {
    int oc = threadIdx.x & 127;
    int half_ = threadIdx.x >> 7;
    int n = blockIdx.y;
    int t0 = blockIdx.x * 128 + half_ * 64;
    float w0 = wf[oc * 2], w1 = wf[oc * 2 + 1];
    const float* xs = seq + (size_t)n * T_LEN;
    unsigned short* ohi = actout + (size_t)(n * 2 + 0) * T_LEN * CH;
    unsigned short* olo = actout + (size_t)(n * 2 + 1) * T_LEN * CH;
    for (int j = 0; j < 64; j++) {
        int t = t0 + j;
        float x1 = xs[t];
        float x0 = (t >= 1) ? xs[t - 1] : 0.f;
        float y = fmaxf(w0 * x0 + w1 * x1, 0.f);
        __half h = __float2half_rn(y);
        __half l = __float2half_rn(y - __half2float(h));
        ohi[(size_t)t * CH + oc] = __half_as_ushort(h);
        olo[(size_t)t * CH + oc] = __half_as_ushort(l);
    }
}

// ---------------- dilated-conv layer: 2-product fp16 MMA ----------------
// smem (u32 units):
//   [0, 17408)        Wh : [tap 2][m 128][68]
//   [17408, 34816)    X  : [buf 2][pl 2][r 64][68]   (buf = tap parity)
//   [34816, 43520)    stage: u16[2 pl][64 t][136 m]
// chunk = 64 t; 8 warps = 4(m of 32) x 2(n of 32); acc persists across taps.
// Products: wh*xh + wh*xl (both f32 acc). Single-wave epilogue.
__global__ void __launch_bounds__(256, 1) layer_mma(
    const unsigned short* __restrict__ actin,
    unsigned short* __restrict__ actout,
    const uint32_t* __restrict__ whi, int d) {
    extern __shared__ uint32_t sm[];
    const uint32_t sb = smem_u32(sm);
    const int tid = threadIdx.x;
    const int lane = tid & 31, wid = tid >> 5;
    const int g = lane >> 2, tq = lane & 3;
    const int n = blockIdx.y;
    const int tbase = blockIdx.x * SPAN;
    const int m0 = (wid & 3) * 32;
    const int n0 = (wid >> 2) * 32;

    // ---- Wh -> smem: 4096 segs of 16B
#pragma unroll
    for (int i = 0; i < 16; i++) {
        int idx = i * 256 + tid;
        int row = idx >> 4, seg = idx & 15;   // row = tap*128 + m
        cpa16(sb + (row * 68 + seg * 4) * 4, whi + row * 64 + seg * 4, 16);
    }
    CP_COMMIT();

    // ---- per-(chunk,tap) X loader: 2 planes x 64 t
    auto load_xt = [&](int it) {
        int c = it >> 1, tap = it & 1, buf = it & 1;
        int tcb = tbase + c * CHUNK;
#pragma unroll
        for (int i = 0; i < 8; i++) {
            int idx = i * 256 + tid;          // 2048 segs
            int pl = idx >> 10, rem = idx & 1023;
            int r = rem >> 4, seg = rem & 15;
            int t = tcb + r - (tap == 0 ? d : 0);
            const unsigned short* src =
                actin + ((size_t)(n * 2 + pl) * T_LEN + (t < 0 ? 0 : t)) * CH + seg * 8;
            cpa16(sb + (17408 + buf * 8704 + pl * 4352 + r * 68 + seg * 4) * 4,
                  src, t >= 0 ? 16 : 0);
        }
        CP_COMMIT();
    };
    load_xt(0);
    load_xt(1);

    CP_WAIT1();          // W + iter0 complete (iter1 in flight)
    __syncthreads();

    unsigned short* stg = (unsigned short*)(sm + 34816);  // [pl][64][136] u16

    float acc[2][2][4][4];   // [product xh/xl][mt][nt][ci]

#pragma unroll 1
    for (int it = 0; it < NITER; it++) {
        const int tap = it & 1, buf = it & 1;
        const uint32_t* Xb = sm + 17408 + buf * 8704;

        if (tap == 0) {
#pragma unroll
            for (int p = 0; p < 2; p++)
#pragma unroll
                for (int mt = 0; mt < 2; mt++)
#pragma unroll
                    for (int nt = 0; nt < 4; nt++)
#pragma unroll
                        for (int j = 0; j < 4; j++) acc[p][mt][nt][j] = 0.f;
        }

        const uint32_t* Wh = sm + tap * 8704;
        const uint32_t* Xh = Xb;
        const uint32_t* Xl = Xb + 4352;
#pragma unroll
        for (int ks = 0; ks < 8; ks++) {
            uint32_t ah[2][4];
            uint32_t bh0[4], bh1[4], bl0[4], bl1[4];
#pragma unroll
            for (int mt = 0; mt < 2; mt++) {
                int r0 = (m0 + mt * 16 + g) * 68, r1 = (m0 + mt * 16 + g + 8) * 68;
                ah[mt][0] = Wh[r0 + ks * 8 + tq];
                ah[mt][1] = Wh[r1 + ks * 8 + tq];
                ah[mt][2] = Wh[r0 + ks * 8 + 4 + tq];
                ah[mt][3] = Wh[r1 + ks * 8 + 4 + tq];
            }
#pragma unroll
            for (int nt = 0; nt < 4; nt++) {
                int xr = (n0 + nt * 8 + g) * 68;
                bh0[nt] = Xh[xr + ks * 8 + tq];
                bh1[nt] = Xh[xr + ks * 8 + 4 + tq];
                bl0[nt] = Xl[xr + ks * 8 + tq];
                bl1[nt] = Xl[xr + ks * 8 + 4 + tq];
            }
            // 16 independent MMAs
#pragma unroll
            for (int mt = 0; mt < 2; mt++)
#pragma unroll
                for (int nt = 0; nt < 4; nt++)
                    mmaf32(acc[0][mt][nt], ah[mt], bh0[nt], bh1[nt]);
#pragma unroll
            for (int mt = 0; mt < 2; mt++)
#pragma unroll
                for (int nt = 0; nt < 4; nt++)
                    mmaf32(acc[1][mt][nt], ah[mt], bl0[nt], bl1[nt]);
        }

        __syncthreads();   // X[buf] reads done; prev stage reads done

        if (it + 2 < NITER) load_xt(it + 2);

        if (tap == 1) {
            const int tcb = tbase + (it >> 1) * CHUNK;
            // single-wave epilogue: every warp writes its (m0, n0) quadrant
#pragma unroll
            for (int mt = 0; mt < 2; mt++)
#pragma unroll
                for (int nt = 0; nt < 4; nt++)
#pragma unroll
                    for (int ci = 0; ci < 4; ci++) {
                        int m = m0 + mt * 16 + g + ((ci >> 1) * 8);
                        int tl = n0 + nt * 8 + tq * 2 + (ci & 1);  // 0..63
                        float y = acc[0][mt][nt][ci] + acc[1][mt][nt][ci];
                        y = fmaxf(y, 0.f);
                        __half hh = __float2half_rn(y);
                        __half ll = __float2half_rn(y - __half2float(hh));
                        stg[tl * 136 + m] = __half_as_ushort(hh);
                        stg[8704 + tl * 136 + m] = __half_as_ushort(ll);
                    }

            if (it + 1 < NITER) {
                if (it + 2 < NITER) CP_WAIT1();
                else CP_WAIT0();
            }
            __syncthreads();   // stage visible + next iter X visible

            // coalesced stores: 2048 uint4, overlap next chunk's MMA
#pragma unroll
            for (int i = 0; i < 8; i++) {
                int idx = i * 256 + tid;
                int pl = idx >> 10, rem = idx & 1023;
                int r = rem >> 4, sg = rem & 15;
                uint4 v = *(const uint4*)(stg + pl * 8704 + r * 136 + sg * 8);
                *(uint4*)(actout + ((size_t)(n * 2 + pl) * T_LEN + tcb + r) * CH +
                          sg * 8) = v;
            }
        } else {
            if (it + 1 < NITER) {
                if (it + 2 < NITER) CP_WAIT1();
                else CP_WAIT0();
            }
            __syncthreads();   // next iter's X visible
        }
    }
}

// ---------------- classifier: 128 -> 256, 2-product, + bias ----------------
// smem (u32): [0,8704) WCh [256 m][... this m-block 128][68] hi plane only;
//             [8704,17408) X [buf2][pl2][32][68]; [17408,21760) stage f32 [128][34]
__global__ void __launch_bounds__(256, 1) cls_mma(
    const unsigned short* __restrict__ actin,
    const uint32_t* __restrict__ wc,
    const float* __restrict__ bias,
    float* __restrict__ out) {
    extern __shared__ uint32_t sm[];
    const uint32_t sb = smem_u32(sm);
    const int tid = threadIdx.x;
    const int lane = tid & 31, wid = tid >> 5;
    const int g = lane >> 2, tq = lane & 3;
    const int n = blockIdx.y;
    const int tbase = blockIdx.x * SPAN;
    const int mz = blockIdx.z * 128;
    const int m0 = (wid & 3) * 32;
    const int n0 = (wid >> 2) * 16;

    // WC hi plane for this m-block: 2048 segs
#pragma unroll
    for (int i = 0; i < 8; i++) {
        int idx = i * 256 + tid;
        int row = idx >> 4, seg = idx & 15;   // row = m 0..127
        cpa16(sb + (row * 68 + seg * 4) * 4,
              wc + (size_t)(mz + row) * 64 + seg * 4, 16);
    }
    CP_COMMIT();

    auto load_x = [&](int c) {
        int buf = c & 1;
        int tcb = tbase + c * CCH;
#pragma unroll
        for (int i = 0; i < 4; i++) {
            int idx = i * 256 + tid;
            int pl = idx >> 9, rem = idx & 511;
            int r = rem >> 4, seg = rem & 15;
            const unsigned short* src =
                actin + ((size_t)(n * 2 + pl) * T_LEN + tcb + r) * CH + seg * 8;
            cpa16(sb + (8704 + buf * 4352 + pl * 2176 + r * 68 + seg * 4) * 4, src, 16);
        }
        CP_COMMIT();
    };
    load_x(0);
    load_x(1);
    CP_WAIT1();
    __syncthreads();

    float* stg = (float*)(sm + 17408);

#pragma unroll 1
    for (int c = 0; c < CNCH; c++) {
        const int buf = c & 1;
        const uint32_t* X = sm + 8704 + buf * 4352;

        float acc[2][2][2][4];
#pragma unroll
        for (int p = 0; p < 2; p++)
#pragma unroll
            for (int mt = 0; mt < 2; mt++)
#pragma unroll
                for (int nt = 0; nt < 2; nt++)
#pragma unroll
                    for (int j = 0; j < 4; j++) acc[p][mt][nt][j] = 0.f;

        const uint32_t* Wh = sm;
        const uint32_t* Xh = X;
        const uint32_t* Xl = X + 2176;
#pragma unroll
        for (int ks = 0; ks < 8; ks++) {
            uint32_t ah[2][4];
            uint32_t bh0[2], bh1[2], bl0[2], bl1[2];
#pragma unroll
            for (int mt = 0; mt < 2; mt++) {
                int r0 = (m0 + mt * 16 + g) * 68, r1 = (m0 + mt * 16 + g + 8) * 68;
                ah[mt][0] = Wh[r0 + ks * 8 + tq];
                ah[mt][1] = Wh[r1 + ks * 8 + tq];
                ah[mt][2] = Wh[r0 + ks * 8 + 4 + tq];
                ah[mt][3] = Wh[r1 + ks * 8 + 4 + tq];
            }
#pragma unroll
            for (int nt = 0; nt < 2; nt++) {
                int xr = (n0 + nt * 8 + g) * 68;
                bh0[nt] = Xh[xr + ks * 8 + tq];
                bh1[nt] = Xh[xr + ks * 8 + 4 + tq];
                bl0[nt] = Xl[xr + ks * 8 + tq];
                bl1[nt] = Xl[xr + ks * 8 + 4 + tq];
            }
#pragma unroll
            for (int mt = 0; mt < 2; mt++)
#pragma unroll
                for (int nt = 0; nt < 2; nt++)
                    mmaf32(acc[0][mt][nt], ah[mt], bh0[nt], bh1[nt]);
#pragma unroll
            for (int mt = 0; mt < 2; mt++)
#pragma unroll
                for (int nt = 0; nt < 2; nt++)
                    mmaf32(acc[1][mt][nt], ah[mt], bl0[nt], bl1[nt]);
        }

        __syncthreads();
        if (c + 2 < CNCH) load_x(c + 2);

#pragma unroll
        for (int mt = 0; mt < 2; mt++)
#pragma unroll
            for (int nt = 0; nt < 2; nt++)
#pragma unroll
                for (int ci = 0; ci < 4; ci++) {
                    int m = m0 + mt * 16 + g + ((ci >> 1) * 8);
                    int tl = n0 + nt * 8 + tq * 2 + (ci & 1);
                    float y = acc[0][mt][nt][ci] + acc[1][mt][nt][ci];
                    stg[m * 34 + tl] = y + __ldg(bias + mz + m);
                }

        if (c + 1 < CNCH) {
            if (c + 2 < CNCH) CP_WAIT1();
            else CP_WAIT0();
        }
        __syncthreads();

        const int tcb = tbase + c * CCH;
#pragma unroll
        for (int i = 0; i < 8; i++) {
            int idx = i * 256 + tid;
            int row = idx >> 4, sg = idx & 15;
            float2 v = *(const float2*)(stg + row * 34 + sg * 2);
            *(float2*)(out + ((size_t)n * NCLS + mz + row) * T_LEN + tcb + sg * 2) = v;
        }
    }
}

// ---------------- launch ----------------
extern "C" void kernel_launch(void* const* d_in, const int* in_sizes, int n_in,
                              void* d_out, int out_size) {
    (void)in_sizes; (void)n_in; (void)out_size;
    const float* seq     = (const float*)d_in[0];
    const float* w_first = (const float*)d_in[1];
    const float* w_rest  = (const float*)d_in[2];
    const float* w_cls   = (const float*)d_in[3];
    const float* b_cls   = (const float*)d_in[4];
    float* out = (float*)d_out;

    unsigned short *a0, *a1;
    uint32_t *whi, *wc;
    cudaGetSymbolAddress((void**)&a0, g_act0);
    cudaGetSymbolAddress((void**)&a1, g_act1);
    cudaGetSymbolAddress((void**)&whi, g_whi);
    cudaGetSymbolAddress((void**)&wc, g_wc);

    const int smem_layer = 43520 * 4;  // 174080 B
    const int smem_cls   = 21760 * 4;  // 87040 B
    cudaFuncSetAttribute(layer_mma, cudaFuncAttributeMaxDynamicSharedMemorySize, smem_layer);
    cudaFuncSetAttribute(cls_mma, cudaFuncAttributeMaxDynamicSharedMemorySize, smem_cls);

    prep_kernel<<<(27 * 2 * 128 * 64 + 255) / 256, 256>>>(w_rest, w_cls, whi, wc);
    layer0_kernel<<<dim3(T_LEN / 128, NB), 256>>>(seq, w_first, a0);

    for (int i = 1; i < 28; i++) {
        int l = i % 14;
        int d = 1 << (l % 10);
        const unsigned short* src = (i & 1) ? a0 : a1;
        unsigned short* dst       = (i & 1) ? a1 : a0;
        layer_mma<<<dim3(NXCTA, NB), 256, smem_layer>>>(
            src, dst, whi + (size_t)(i - 1) * 2 * 128 * 64, d);
    }

    cls_mma<<<dim3(NXCTA, NB, 2), 256, smem_cls>>>(a1, wc, b_cls, out);
}